// round 12
// baseline (speedup 1.0000x reference)
#include <cuda_runtime.h>
#include <cuda_bf16.h>
#include <mma.h>
#include <math_constants.h>
#include <cstdint>

using namespace nvcuda;

#define NPTS 1024
#define HA   256

// ---------------- persistent device scratch ----------------
__device__ float g_qa[NPTS * HA];
__device__ float g_ka[NPTS * HA];
__device__ float g_vp[NPTS * 64];
__device__ float g_pW2a[64 * HA];
__device__ __nv_bfloat16 g_w1phi[64 * 320], g_w1plo[64 * 320]; // [pW2a | pW2] by k
__device__ __nv_bfloat16 g_w2Thi[64 * 256], g_w2Tlo[64 * 256]; // aW2^T [d][n]

__device__ __forceinline__ void split2(float x, __nv_bfloat16& h, __nv_bfloat16& l) {
    h = __float2bfloat16(x);
    l = __float2bfloat16(x - __bfloat162float(h));
}
__device__ __forceinline__ uint32_t pack_bf2(__nv_bfloat16 a, __nv_bfloat16 b) {
    __nv_bfloat162 t; t.x = a; t.y = b;
    return *reinterpret_cast<uint32_t*>(&t);
}

// ---------------- prep kernels ----------------
__global__ void prep_pw2a(const float* __restrict__ pW2, const float* __restrict__ aW1) {
    int k = blockIdx.x, n = threadIdx.x;
    float s = 0.f;
    #pragma unroll 16
    for (int c = 0; c < 64; ++c) s = fmaf(pW2[k * 64 + c], aW1[c * 256 + n], s);
    g_pW2a[k * 256 + n] = s;
}

__global__ void prep_qkv(const float* __restrict__ x,  const float* __restrict__ Wq,
                         const float* __restrict__ Wk, const float* __restrict__ Wv,
                         const float* __restrict__ aW1, const float* __restrict__ ab1,
                         const float* __restrict__ pb2) {
    __shared__ float sx[64], sq[64], sk[64];
    int i = blockIdx.x, t = threadIdx.x;
    if (t < 64) sx[t] = x[i * 64 + t];
    __syncthreads();
    if (t < 64) {
        float aq = 0.f, ak = 0.f, av = 0.f;
        #pragma unroll 16
        for (int c = 0; c < 64; ++c) {
            float xc = sx[c];
            aq = fmaf(xc, Wq[c * 64 + t], aq);
            ak = fmaf(xc, Wk[c * 64 + t], ak);
            av = fmaf(xc, Wv[c * 64 + t], av);
        }
        sq[t] = aq; sk[t] = ak;
        g_vp[i * 64 + t] = av + pb2[t];
    }
    __syncthreads();
    int n = t;
    float accq = 0.f, acck = 0.f, accb = 0.f;
    #pragma unroll 8
    for (int c = 0; c < 64; ++c) {
        float w = aW1[c * 256 + n];
        accq = fmaf(sq[c], w, accq);
        acck = fmaf(sk[c], w, acck);
        accb = fmaf(pb2[c], w, accb);
    }
    g_qa[i * HA + n] = accq + ab1[n] + accb;
    g_ka[i * HA + n] = acck;
}

__global__ void prep_wsplit(const float* __restrict__ pW2, const float* __restrict__ aW2) {
    int t = blockIdx.x * 256 + threadIdx.x;   // grid 80 -> 0..20479
    if (t < 64 * 320) {
        int k = t / 320, cc = t % 320;
        float w = (cc < 256) ? g_pW2a[k * 256 + cc] : pW2[k * 64 + (cc - 256)];
        __nv_bfloat16 h, l; split2(w, h, l);
        g_w1phi[t] = h; g_w1plo[t] = l;
    }
    if (t < 64 * 256) {
        int d = t >> 8, n = t & 255;   // W2T[d][n] = aW2[n][d]
        __nv_bfloat16 h, l; split2(aW2[n * 64 + d], h, l);
        g_w2Thi[t] = h; g_w2Tlo[t] = l;
    }
}

// ---------------- smem byte offsets ----------------
#define SM_W1HI  0u        /* 64 x 328 bf16 = 41984 */
#define SM_W1LO  41984u
#define SM_W2THI 83968u    /* 64 x 264 bf16 = 33792 */
#define SM_W2TLO 117760u
#define SM_HHI   151552u   /* 64 x 72 bf16 = 9216 */
#define SM_HLO   160768u
#define SM_HIDH  169984u   /* 64 x 72 bf16 = 9216 */
#define SM_HIDL  179200u
#define SM_G1    188416u   /* 64 x 136 f32 = 34816 */
#define SM_QA    223232u   /* 256 f32 */
#define SMEM_BYTES 224256u
// overlays: rpe final (f32 64x68) over H region; simP0 over Hid; simP1 over G1
#define SM_RPEF  SM_HHI
#define SM_SIMP0 SM_HIDH
#define SM_SIMP1 SM_G1

extern __shared__ char smc[];

#define MMA3(accf, ah, al, bh, bl) do { \
    wmma::mma_sync(accf, ah, bh, accf); \
    wmma::mma_sync(accf, al, bh, accf); \
    wmma::mma_sync(accf, ah, bl, accf); } while (0)

__global__ __launch_bounds__(256, 1)
void pt_main(const float* __restrict__ pos, const float* __restrict__ pW1,
             const float* __restrict__ pb1, float* __restrict__ out) {
    const int i = blockIdx.x, tid = threadIdx.x;
    const int wid = tid >> 5;

    __nv_bfloat16* sW1hi = (__nv_bfloat16*)(smc + SM_W1HI);
    __nv_bfloat16* sW1lo = (__nv_bfloat16*)(smc + SM_W1LO);
    __nv_bfloat16* sW2hi = (__nv_bfloat16*)(smc + SM_W2THI);
    __nv_bfloat16* sW2lo = (__nv_bfloat16*)(smc + SM_W2TLO);
    __nv_bfloat16* sHhi  = (__nv_bfloat16*)(smc + SM_HHI);
    __nv_bfloat16* sHlo  = (__nv_bfloat16*)(smc + SM_HLO);
    __nv_bfloat16* sHidh = (__nv_bfloat16*)(smc + SM_HIDH);
    __nv_bfloat16* sHidl = (__nv_bfloat16*)(smc + SM_HIDL);
    float* sG1   = (float*)(smc + SM_G1);
    float* sQa   = (float*)(smc + SM_QA);
    float* sRpeF = (float*)(smc + SM_RPEF);
    float* sSimP0 = (float*)(smc + SM_SIMP0);
    float* sSimP1 = (float*)(smc + SM_SIMP1);

    // ---- stage weights ----
    {   // W1': 64 x 320 -> stride 328 elems (656B rows, 41 uint4)
        const uint4* s1 = (const uint4*)g_w1phi;
        const uint4* s2 = (const uint4*)g_w1plo;
        for (int u = tid; u < 64 * 40; u += 256) {
            int r = u / 40, q = u % 40;
            *(uint4*)(smc + SM_W1HI + r * 656 + q * 16) = s1[u];
            *(uint4*)(smc + SM_W1LO + r * 656 + q * 16) = s2[u];
        }
    }
    {   // W2T: 64 x 256 -> stride 264 elems (528B rows)
        const uint4* s1 = (const uint4*)g_w2Thi;
        const uint4* s2 = (const uint4*)g_w2Tlo;
        for (int u = tid; u < 64 * 32; u += 256) {
            int r = u >> 5, q = u & 31;
            *(uint4*)(smc + SM_W2THI + r * 528 + q * 16) = s1[u];
            *(uint4*)(smc + SM_W2TLO + r * 528 + q * 16) = s2[u];
        }
    }
    sQa[tid] = g_qa[i * 256 + tid];
    __shared__ float sPW1[128], sPb1[64];
    if (tid < 128) sPW1[tid] = pW1[tid];
    if (tid < 64)  sPb1[tid] = pb1[tid];

    const float pix = __ldg(pos + i * 2 + 0);
    const float piy = __ldg(pos + i * 2 + 1);

    // warp mappings
    const int wm = wid & 1, wn = wid >> 1;                       // GEMM1: m-half, n-slot(32w)
    const int wm2 = wid & 1, wn2 = (wid >> 1) & 1, wk2 = wid >> 2; // GEMM2
    const bool doR = (wid < 4);                                  // rpe warps (1/SMSP)
    // elementwise mappings
    const int jT = tid >> 2, c0 = (tid & 3) * 16;
    const int d_e = tid & 63, jg = tid >> 6;

    float m_run = -CUDART_INF_F, l_run = 0.f, num_run = 0.f;

    wmma::fragment<wmma::matrix_a, 16, 16, 16, __nv_bfloat16, wmma::row_major> Ah0, Ah1, Al0, Al1;
    wmma::fragment<wmma::matrix_b, 16, 16, 16, __nv_bfloat16, wmma::row_major> Bh, Bl;
    wmma::fragment<wmma::matrix_b, 16, 16, 16, __nv_bfloat16, wmma::col_major> Cbh, Cbl;

    __syncthreads();

    for (int c = 0; c < 16; ++c) {
        const int jbase = c * 64;
        __syncthreads();   // prev chunk softmax done with overlays

        // ---- Phase A: H[j][k] hi/lo, stride 72; thread: 1 j x 16 k ----
        {
            float2 pj = __ldg(reinterpret_cast<const float2*>(pos + (jbase + jT) * 2));
            float dx = pix - pj.x, dy = piy - pj.y;
            uint32_t ph[8], pl[8];
            #pragma unroll
            for (int t = 0; t < 16; t += 2) {
                int k0 = c0 + t;
                float h0 = fmaxf(fmaf(dx, sPW1[k0],     fmaf(dy, sPW1[64 + k0],     sPb1[k0])),     0.f);
                float h1 = fmaxf(fmaf(dx, sPW1[k0 + 1], fmaf(dy, sPW1[64 + k0 + 1], sPb1[k0 + 1])), 0.f);
                __nv_bfloat16 a, b, al, bl;
                split2(h0, a, al); split2(h1, b, bl);
                ph[t >> 1] = pack_bf2(a, b);
                pl[t >> 1] = pack_bf2(al, bl);
            }
            *reinterpret_cast<uint4*>(sHhi + jT * 72 + c0)     = make_uint4(ph[0], ph[1], ph[2], ph[3]);
            *reinterpret_cast<uint4*>(sHhi + jT * 72 + c0 + 8) = make_uint4(ph[4], ph[5], ph[6], ph[7]);
            *reinterpret_cast<uint4*>(sHlo + jT * 72 + c0)     = make_uint4(pl[0], pl[1], pl[2], pl[3]);
            *reinterpret_cast<uint4*>(sHlo + jT * 72 + c0 + 8) = make_uint4(pl[4], pl[5], pl[6], pl[7]);
        }
        __syncthreads();

        // ---- mega GEMM1 (both 128-col pairs in registers) + folded rpe ----
        wmma::fragment<wmma::accumulator, 16, 16, 16, float> acc[2][2][2]; // [pair][msub][nsub]
        wmma::fragment<wmma::accumulator, 16, 16, 16, float> rpe[2][2];
        #pragma unroll
        for (int p = 0; p < 2; ++p)
            #pragma unroll
            for (int ms = 0; ms < 2; ++ms)
                #pragma unroll
                for (int ns = 0; ns < 2; ++ns) wmma::fill_fragment(acc[p][ms][ns], 0.f);
        if (doR) {
            #pragma unroll
            for (int ms = 0; ms < 2; ++ms)
                #pragma unroll
                for (int ns = 0; ns < 2; ++ns) wmma::fill_fragment(rpe[ms][ns], 0.f);
        }

        #pragma unroll
        for (int k = 0; k < 4; ++k) {
            wmma::load_matrix_sync(Ah0, sHhi + (wm * 32) * 72 + k * 16, 72);
            wmma::load_matrix_sync(Ah1, sHhi + (wm * 32 + 16) * 72 + k * 16, 72);
            wmma::load_matrix_sync(Al0, sHlo + (wm * 32) * 72 + k * 16, 72);
            wmma::load_matrix_sync(Al1, sHlo + (wm * 32 + 16) * 72 + k * 16, 72);
            #pragma unroll
            for (int p = 0; p < 2; ++p) {
                #pragma unroll
                for (int ns = 0; ns < 2; ++ns) {
                    const int col = p * 128 + wn * 32 + ns * 16;
                    wmma::load_matrix_sync(Bh, sW1hi + (k * 16) * 328 + col, 328);
                    wmma::load_matrix_sync(Bl, sW1lo + (k * 16) * 328 + col, 328);
                    MMA3(acc[p][0][ns], Ah0, Al0, Bh, Bl);
                    MMA3(acc[p][1][ns], Ah1, Al1, Bh, Bl);
                }
            }
            if (doR) {
                #pragma unroll
                for (int ns = 0; ns < 2; ++ns) {
                    const int col = 256 + wn * 32 + ns * 16;
                    wmma::load_matrix_sync(Bh, sW1hi + (k * 16) * 328 + col, 328);
                    wmma::load_matrix_sync(Bl, sW1lo + (k * 16) * 328 + col, 328);
                    MMA3(rpe[0][ns], Ah0, Al0, Bh, Bl);
                    MMA3(rpe[1][ns], Ah1, Al1, Bh, Bl);
                }
            }
        }
        __syncthreads();   // all H reads done -> H region writable (rpe overlay)

        if (doR) {
            #pragma unroll
            for (int ms = 0; ms < 2; ++ms)
                #pragma unroll
                for (int ns = 0; ns < 2; ++ns)
                    wmma::store_matrix_sync(sRpeF + (wm * 32 + ms * 16) * 68 + wn * 32 + ns * 16,
                                            rpe[ms][ns], 68, wmma::mem_row_major);
        }

        wmma::fragment<wmma::accumulator, 16, 16, 16, float> sim[2][2];
        #pragma unroll
        for (int ms = 0; ms < 2; ++ms)
            #pragma unroll
            for (int ns = 0; ns < 2; ++ns) wmma::fill_fragment(sim[ms][ns], 0.f);

        #pragma unroll 1
        for (int p = 0; p < 2; ++p) {
            // store this pair's GEMM1 result into G1 (cols split into two 68-wide halves)
            #pragma unroll
            for (int ms = 0; ms < 2; ++ms)
                #pragma unroll
                for (int ns = 0; ns < 2; ++ns) {
                    const int g1c = (wn >> 1) * 68 + (wn & 1) * 32 + ns * 16;
                    wmma::store_matrix_sync(sG1 + (wm * 32 + ms * 16) * 136 + g1c,
                                            acc[p][ms][ns], 136, wmma::mem_row_major);
                }
            __syncthreads();

            #pragma unroll 1
            for (int h = 0; h < 2; ++h) {
                const int s = p * 2 + h;
                // ---- epilogue: +qa -ka, relu, split -> Hid (strip s) ----
                {
                    const float* g1p = sG1 + jT * 136 + h * 68 + c0;
                    float4 ga = *reinterpret_cast<const float4*>(g1p);
                    float4 gb = *reinterpret_cast<const float4*>(g1p + 4);
                    float4 gc = *reinterpret_cast<const float4*>(g1p + 8);
                    float4 gd = *reinterpret_cast<const float4*>(g1p + 12);
                    const float* qp = sQa + s * 64 + c0;
                    float4 q0 = *reinterpret_cast<const float4*>(qp);
                    float4 q1 = *reinterpret_cast<const float4*>(qp + 4);
                    float4 q2 = *reinterpret_cast<const float4*>(qp + 8);
                    float4 q3 = *reinterpret_cast<const float4*>(qp + 12);
                    const float4* kap = reinterpret_cast<const float4*>(
                        g_ka + (size_t)(jbase + jT) * 256 + s * 64 + c0);
                    float4 k0 = __ldg(kap), k1 = __ldg(kap + 1), k2 = __ldg(kap + 2), k3 = __ldg(kap + 3);
                    float v[16];
                    v[0]  = fmaxf(ga.x + q0.x - k0.x, 0.f);
                    v[1]  = fmaxf(ga.y + q0.y - k0.y, 0.f);
                    v[2]  = fmaxf(ga.z + q0.z - k0.z, 0.f);
                    v[3]  = fmaxf(ga.w + q0.w - k0.w, 0.f);
                    v[4]  = fmaxf(gb.x + q1.x - k1.x, 0.f);
                    v[5]  = fmaxf(gb.y + q1.y - k1.y, 0.f);
                    v[6]  = fmaxf(gb.z + q1.z - k1.z, 0.f);
                    v[7]  = fmaxf(gb.w + q1.w - k1.w, 0.f);
                    v[8]  = fmaxf(gc.x + q2.x - k2.x, 0.f);
                    v[9]  = fmaxf(gc.y + q2.y - k2.y, 0.f);
                    v[10] = fmaxf(gc.z + q2.z - k2.z, 0.f);
                    v[11] = fmaxf(gc.w + q2.w - k2.w, 0.f);
                    v[12] = fmaxf(gd.x + q3.x - k3.x, 0.f);
                    v[13] = fmaxf(gd.y + q3.y - k3.y, 0.f);
                    v[14] = fmaxf(gd.z + q3.z - k3.z, 0.f);
                    v[15] = fmaxf(gd.w + q3.w - k3.w, 0.f);
                    uint32_t ph[8], pl[8];
                    #pragma unroll
                    for (int t = 0; t < 8; ++t) {
                        __nv_bfloat16 a, b, al, bl;
                        split2(v[t * 2], a, al); split2(v[t * 2 + 1], b, bl);
                        ph[t] = pack_bf2(a, b); pl[t] = pack_bf2(al, bl);
                    }
                    *reinterpret_cast<uint4*>(sHidh + jT * 72 + c0)     = make_uint4(ph[0], ph[1], ph[2], ph[3]);
                    *reinterpret_cast<uint4*>(sHidh + jT * 72 + c0 + 8) = make_uint4(ph[4], ph[5], ph[6], ph[7]);
                    *reinterpret_cast<uint4*>(sHidl + jT * 72 + c0)     = make_uint4(pl[0], pl[1], pl[2], pl[3]);
                    *reinterpret_cast<uint4*>(sHidl + jT * 72 + c0 + 8) = make_uint4(pl[4], pl[5], pl[6], pl[7]);
                }
                __syncthreads();

                // ---- GEMM2 strip s: sim += Hid @ W2T (split-k 2, 32x32 tiles) ----
                #pragma unroll
                for (int kf = 0; kf < 2; ++kf) {
                    const int kloc = wk2 * 32 + kf * 16;
                    wmma::load_matrix_sync(Ah0, sHidh + (wm2 * 32) * 72 + kloc, 72);
                    wmma::load_matrix_sync(Ah1, sHidh + (wm2 * 32 + 16) * 72 + kloc, 72);
                    wmma::load_matrix_sync(Al0, sHidl + (wm2 * 32) * 72 + kloc, 72);
                    wmma::load_matrix_sync(Al1, sHidl + (wm2 * 32 + 16) * 72 + kloc, 72);
                    #pragma unroll
                    for (int ns = 0; ns < 2; ++ns) {
                        const int d0 = wn2 * 32 + ns * 16;
                        wmma::load_matrix_sync(Cbh, sW2hi + d0 * 264 + s * 64 + kloc, 264);
                        wmma::load_matrix_sync(Cbl, sW2lo + d0 * 264 + s * 64 + kloc, 264);
                        MMA3(sim[0][ns], Ah0, Al0, Cbh, Cbl);
                        MMA3(sim[1][ns], Ah1, Al1, Cbh, Cbl);
                    }
                }
                __syncthreads();   // Hid reusable
            }
        }

        // ---- sim partial stores: wk2=0 -> Hid overlay, wk2=1 -> G1 overlay ----
        {
            float* dst = wk2 ? sSimP1 : sSimP0;
            #pragma unroll
            for (int ms = 0; ms < 2; ++ms)
                #pragma unroll
                for (int ns = 0; ns < 2; ++ns)
                    wmma::store_matrix_sync(dst + (wm2 * 32 + ms * 16) * 68 + wn2 * 32 + ns * 16,
                                            sim[ms][ns], 68, wmma::mem_row_major);
        }
        __syncthreads();

        // ---- channel-wise online softmax over 64 j (16 j per thread) ----
        #pragma unroll 4
        for (int jj = 0; jj < 16; ++jj) {
            int j = jg * 16 + jj;
            float s  = sSimP0[j * 68 + d_e] + sSimP1[j * 68 + d_e];
            float vv = __ldg(g_vp + (size_t)(jbase + j) * 64 + d_e) + sRpeF[j * 68 + d_e];
            float mn = fmaxf(m_run, s);
            float cs = __expf(m_run - mn);
            float pe = __expf(s - mn);
            l_run   = fmaf(l_run, cs, pe);
            num_run = fmaf(num_run, cs, pe * vv);
            m_run   = mn;
        }
    }

    // ---- final cross-group merge (4 groups; reuse rpe overlay) ----
    __syncthreads();
    float* sRed = sRpeF;
    sRed[jg * 64 + d_e]       = m_run;
    sRed[256 + jg * 64 + d_e] = l_run;
    sRed[512 + jg * 64 + d_e] = num_run;
    __syncthreads();
    if (tid < 64) {
        float M = -CUDART_INF_F;
        #pragma unroll
        for (int s2 = 0; s2 < 4; ++s2) M = fmaxf(M, sRed[s2 * 64 + tid]);
        float L = 0.f, NU = 0.f;
        #pragma unroll
        for (int s2 = 0; s2 < 4; ++s2) {
            float e = __expf(sRed[s2 * 64 + tid] - M);
            L  = fmaf(sRed[256 + s2 * 64 + tid], e, L);
            NU = fmaf(sRed[512 + s2 * 64 + tid], e, NU);
        }
        out[i * 64 + tid] = NU / L;
    }
}

// ---------------- launch ----------------
extern "C" void kernel_launch(void* const* d_in, const int* in_sizes, int n_in,
                              void* d_out, int out_size) {
    const float* x   = (const float*)d_in[0];
    const float* pos = (const float*)d_in[1];
    const float* Wq  = (const float*)d_in[2];
    const float* Wk  = (const float*)d_in[3];
    const float* Wv  = (const float*)d_in[4];
    const float* pW1 = (const float*)d_in[5];
    const float* pb1 = (const float*)d_in[6];
    const float* pW2 = (const float*)d_in[7];
    const float* pb2 = (const float*)d_in[8];
    const float* aW1 = (const float*)d_in[9];
    const float* ab1 = (const float*)d_in[10];
    const float* aW2 = (const float*)d_in[11];
    // d_in[12] = ab2: constant over j per channel -> cancels in softmax (exact), unused.
    float* out = (float*)d_out;

    cudaFuncSetAttribute(pt_main, cudaFuncAttributeMaxDynamicSharedMemorySize, SMEM_BYTES);

    prep_pw2a<<<64, 256>>>(pW2, aW1);
    prep_qkv<<<NPTS, 256>>>(x, Wq, Wk, Wv, aW1, ab1, pb2);
    prep_wsplit<<<80, 256>>>(pW2, aW2);
    pt_main<<<NPTS, 256, SMEM_BYTES>>>(pos, pW1, pb1, out);
}

// round 15
// speedup vs baseline: 1.2334x; 1.2334x over previous
#include <cuda_runtime.h>
#include <cuda_bf16.h>
#include <mma.h>
#include <math_constants.h>
#include <cstdint>

using namespace nvcuda;

#define NPTS 1024
#define HA   256

// ---------------- persistent device scratch ----------------
__device__ float g_qa[NPTS * HA];
__device__ float g_ka[NPTS * HA];
__device__ float g_vp[NPTS * 64];
__device__ float g_pW2a[64 * HA];
__device__ __nv_bfloat16 g_w1hi[64 * 256], g_w1lo[64 * 256];   // pW2a [k][n]
__device__ __nv_bfloat16 g_wphi[64 * 64],  g_wplo[64 * 64];    // pW2  [k][d]
__device__ __nv_bfloat16 g_w2Thi[64 * 256], g_w2Tlo[64 * 256]; // aW2^T [d][n]

__device__ __forceinline__ void split2(float x, __nv_bfloat16& h, __nv_bfloat16& l) {
    h = __float2bfloat16(x);
    l = __float2bfloat16(x - __bfloat162float(h));
}
__device__ __forceinline__ uint32_t pack_bf2(__nv_bfloat16 a, __nv_bfloat16 b) {
    __nv_bfloat162 t; t.x = a; t.y = b;
    return *reinterpret_cast<uint32_t*>(&t);
}

// ---------------- prep kernels ----------------
__global__ void prep_pw2a(const float* __restrict__ pW2, const float* __restrict__ aW1) {
    int k = blockIdx.x, n = threadIdx.x;
    float s = 0.f;
    #pragma unroll 16
    for (int c = 0; c < 64; ++c) s = fmaf(pW2[k * 64 + c], aW1[c * 256 + n], s);
    g_pW2a[k * 256 + n] = s;
}

__global__ void prep_qkv(const float* __restrict__ x,  const float* __restrict__ Wq,
                         const float* __restrict__ Wk, const float* __restrict__ Wv,
                         const float* __restrict__ aW1, const float* __restrict__ ab1,
                         const float* __restrict__ pb2) {
    __shared__ float sx[64], sq[64], sk[64];
    int i = blockIdx.x, t = threadIdx.x;
    if (t < 64) sx[t] = x[i * 64 + t];
    __syncthreads();
    if (t < 64) {
        float aq = 0.f, ak = 0.f, av = 0.f;
        #pragma unroll 16
        for (int c = 0; c < 64; ++c) {
            float xc = sx[c];
            aq = fmaf(xc, Wq[c * 64 + t], aq);
            ak = fmaf(xc, Wk[c * 64 + t], ak);
            av = fmaf(xc, Wv[c * 64 + t], av);
        }
        sq[t] = aq; sk[t] = ak;
        g_vp[i * 64 + t] = av + pb2[t];
    }
    __syncthreads();
    int n = t;
    float accq = 0.f, acck = 0.f, accb = 0.f;
    #pragma unroll 8
    for (int c = 0; c < 64; ++c) {
        float w = aW1[c * 256 + n];
        accq = fmaf(sq[c], w, accq);
        acck = fmaf(sk[c], w, acck);
        accb = fmaf(pb2[c], w, accb);
    }
    g_qa[i * HA + n] = accq + ab1[n] + accb;
    g_ka[i * HA + n] = acck;
}

__global__ void prep_wsplit(const float* __restrict__ pW2, const float* __restrict__ aW2) {
    int t = blockIdx.x * 256 + threadIdx.x;   // grid 64 -> 0..16383
    {
        __nv_bfloat16 h, l; split2(g_pW2a[t], h, l);
        g_w1hi[t] = h; g_w1lo[t] = l;
    }
    if (t < 4096) {
        __nv_bfloat16 h, l; split2(pW2[t], h, l);
        g_wphi[t] = h; g_wplo[t] = l;
    }
    {
        int d = t >> 8, n = t & 255;   // W2T[d][n] = aW2[n][d]
        __nv_bfloat16 h, l; split2(aW2[n * 64 + d], h, l);
        g_w2Thi[t] = h; g_w2Tlo[t] = l;
    }
}

// ---------------- smem byte offsets (identical to R9/1311.8 kernel) ----------------
#define SM_W1HI  0u        /* 64 x 264 bf16 = 33792 */
#define SM_W1LO  33792u
#define SM_WPHI  67584u    /* 64 x 72 bf16 = 9216 */
#define SM_WPLO  76800u
#define SM_W2THI 86016u    /* 64 x 264 bf16 = 33792 */
#define SM_W2TLO 119808u
#define SM_HHI   153600u   /* 64 x 72 bf16 = 9216 */
#define SM_HLO   162816u
#define SM_G1    172032u   /* 64 x 136 f32 = 34816 (GEMM1 strip pair / sim partials) */
#define SM_HIDH  206848u   /* 64 x 72 bf16 = 9216 */
#define SM_HIDL  216064u
#define SM_QA    225280u   /* 256 f32 */
#define SMEM_BYTES 226304u
#define SM_RPE   SM_HIDH   /* 64 x 68 f32 overlay (Hid dead by then) */

extern __shared__ char smc[];

#define MMA3(accf, ah, al, bh, bl) do { \
    wmma::mma_sync(accf, ah, bh, accf); \
    wmma::mma_sync(accf, al, bh, accf); \
    wmma::mma_sync(accf, ah, bl, accf); } while (0)

__global__ __launch_bounds__(512, 1)
void pt_main(const float* __restrict__ pos, const float* __restrict__ pW1,
             const float* __restrict__ pb1, float* __restrict__ out) {
    const int i = blockIdx.x, tid = threadIdx.x;
    const int wid = tid >> 5;

    __nv_bfloat16* sW1hi = (__nv_bfloat16*)(smc + SM_W1HI);
    __nv_bfloat16* sW1lo = (__nv_bfloat16*)(smc + SM_W1LO);
    __nv_bfloat16* sWphi = (__nv_bfloat16*)(smc + SM_WPHI);
    __nv_bfloat16* sWplo = (__nv_bfloat16*)(smc + SM_WPLO);
    __nv_bfloat16* sW2hi = (__nv_bfloat16*)(smc + SM_W2THI);
    __nv_bfloat16* sW2lo = (__nv_bfloat16*)(smc + SM_W2TLO);
    __nv_bfloat16* sHhi  = (__nv_bfloat16*)(smc + SM_HHI);
    __nv_bfloat16* sHlo  = (__nv_bfloat16*)(smc + SM_HLO);
    float* sG1   = (float*)(smc + SM_G1);
    __nv_bfloat16* sHidh = (__nv_bfloat16*)(smc + SM_HIDH);
    __nv_bfloat16* sHidl = (__nv_bfloat16*)(smc + SM_HIDL);
    float* sQa   = (float*)(smc + SM_QA);
    float* sRpe  = (float*)(smc + SM_RPE);

    // ---- stage weights ----
    {   // W1: 64x256 -> stride 264
        const unsigned long long* s1 = (const unsigned long long*)g_w1hi;
        const unsigned long long* s2 = (const unsigned long long*)g_w1lo;
        for (int u = tid; u < 64 * 64; u += 512) {
            int r = u >> 6, c4 = (u & 63) * 4;
            *(unsigned long long*)(sW1hi + r * 264 + c4) = s1[u];
            *(unsigned long long*)(sW1lo + r * 264 + c4) = s2[u];
        }
    }
    {   // Wp: 64x64 -> stride 72
        const unsigned long long* s1 = (const unsigned long long*)g_wphi;
        const unsigned long long* s2 = (const unsigned long long*)g_wplo;
        for (int u = tid; u < 64 * 16; u += 512) {
            int r = u >> 4, c4 = (u & 15) * 4;
            *(unsigned long long*)(sWphi + r * 72 + c4) = s1[u];
            *(unsigned long long*)(sWplo + r * 72 + c4) = s2[u];
        }
    }
    {   // W2T: 64x256 -> stride 264
        const unsigned long long* s1 = (const unsigned long long*)g_w2Thi;
        const unsigned long long* s2 = (const unsigned long long*)g_w2Tlo;
        for (int u = tid; u < 64 * 64; u += 512) {
            int r = u >> 6, c4 = (u & 63) * 4;
            *(unsigned long long*)(sW2hi + r * 264 + c4) = s1[u];
            *(unsigned long long*)(sW2lo + r * 264 + c4) = s2[u];
        }
    }
    for (int t = tid; t < 256; t += 512) sQa[t] = g_qa[i * 256 + t];
    __shared__ float sPW1[128], sPb1[64];
    if (tid < 128) sPW1[tid] = pW1[tid];
    if (tid < 64)  sPb1[tid] = pb1[tid];

    const float pix = __ldg(pos + i * 2 + 0);
    const float piy = __ldg(pos + i * 2 + 1);

    // GEMM1 mapping (unchanged from R9): 16 distinct slots
    const int sg = wid >> 3;            // strip-in-pair (n 64-block)
    const int wm = (wid >> 2) & 1;      // m-half (32 rows)
    const int wn = wid & 3;             // 16-col block
    // GEMM2 mapping (FIXED: 16 distinct slots, no duplication)
    const int g2m = wid & 1;            // m-half (32 rows)
    const int g2n = (wid >> 1) & 3;     // 16-col block (d)
    const int g2k = wid >> 3;           // k-half within strip
    // rpe mapping: 4x4 grid of 16x16 tiles, all 16 warps
    const int rr = (wid >> 2) * 16, rc = (wid & 3) * 16;
    // elementwise mappings
    const int jT = tid >> 3, c0T = (tid & 7) * 8;
    const int d_e = tid & 63, jg = tid >> 6;

    float m_run = -CUDART_INF_F, l_run = 0.f, num_run = 0.f;

    wmma::fragment<wmma::matrix_a, 16, 16, 16, __nv_bfloat16, wmma::row_major> Ah0, Ah1, Al0, Al1;
    wmma::fragment<wmma::matrix_b, 16, 16, 16, __nv_bfloat16, wmma::row_major> Bh, Bl;
    wmma::fragment<wmma::matrix_b, 16, 16, 16, __nv_bfloat16, wmma::col_major> Cbh, Cbl;
    wmma::fragment<wmma::accumulator, 16, 16, 16, float> acc0, acc1, sim0, sim1;

    __syncthreads();

    for (int c = 0; c < 16; ++c) {
        const int jbase = c * 64;
        __syncthreads();   // prev chunk softmax done with overlays

        // ---- Phase A: H[j][k] hi/lo bf16, stride 72 (thread: 1 j x 8 k) ----
        {
            float2 pj = __ldg(reinterpret_cast<const float2*>(pos + (jbase + jT) * 2));
            float dx = pix - pj.x, dy = piy - pj.y;
            uint32_t ph[4], pl[4];
            #pragma unroll
            for (int t = 0; t < 8; t += 2) {
                int k0 = c0T + t;
                float h0 = fmaxf(fmaf(dx, sPW1[k0],     fmaf(dy, sPW1[64 + k0],     sPb1[k0])),     0.f);
                float h1 = fmaxf(fmaf(dx, sPW1[k0 + 1], fmaf(dy, sPW1[64 + k0 + 1], sPb1[k0 + 1])), 0.f);
                __nv_bfloat16 a, b, al, bl;
                split2(h0, a, al); split2(h1, b, bl);
                ph[t >> 1] = pack_bf2(a, b);
                pl[t >> 1] = pack_bf2(al, bl);
            }
            *reinterpret_cast<uint4*>(sHhi + jT * 72 + c0T) = make_uint4(ph[0], ph[1], ph[2], ph[3]);
            *reinterpret_cast<uint4*>(sHlo + jT * 72 + c0T) = make_uint4(pl[0], pl[1], pl[2], pl[3]);
        }
        __syncthreads();   // H ready

        wmma::fill_fragment(sim0, 0.f);
        wmma::fill_fragment(sim1, 0.f);

        // ---- 2 strip-pairs: GEMM1 (32x16 warp tiles, 2 strips concurrently) ----
        #pragma unroll 1
        for (int pair = 0; pair < 2; ++pair) {
            const int n0 = (pair * 2 + sg) * 64;
            wmma::fill_fragment(acc0, 0.f);
            wmma::fill_fragment(acc1, 0.f);
            #pragma unroll
            for (int k = 0; k < 4; ++k) {
                wmma::load_matrix_sync(Ah0, sHhi + (wm * 32) * 72 + k * 16, 72);
                wmma::load_matrix_sync(Ah1, sHhi + (wm * 32 + 16) * 72 + k * 16, 72);
                wmma::load_matrix_sync(Al0, sHlo + (wm * 32) * 72 + k * 16, 72);
                wmma::load_matrix_sync(Al1, sHlo + (wm * 32 + 16) * 72 + k * 16, 72);
                wmma::load_matrix_sync(Bh, sW1hi + k * 16 * 264 + n0 + wn * 16, 264);
                wmma::load_matrix_sync(Bl, sW1lo + k * 16 * 264 + n0 + wn * 16, 264);
                wmma::mma_sync(acc0, Ah0, Bh, acc0);
                wmma::mma_sync(acc0, Al0, Bh, acc0);
                wmma::mma_sync(acc0, Ah0, Bl, acc0);
                wmma::mma_sync(acc1, Ah1, Bh, acc1);
                wmma::mma_sync(acc1, Al1, Bh, acc1);
                wmma::mma_sync(acc1, Ah1, Bl, acc1);
            }
            wmma::store_matrix_sync(sG1 + (wm * 32) * 136 + sg * 68 + wn * 16, acc0, 136, wmma::mem_row_major);
            wmma::store_matrix_sync(sG1 + (wm * 32 + 16) * 136 + sg * 68 + wn * 16, acc1, 136, wmma::mem_row_major);
            __syncthreads();

            // ---- per strip: epilogue -> Hid, then GEMM2 accumulate (split-k 2, de-duped) ----
            #pragma unroll 1
            for (int h = 0; h < 2; ++h) {
                const int s = pair * 2 + h;
                const int n0q = s * 64;
                {
                    float4 g4a = *reinterpret_cast<const float4*>(sG1 + jT * 136 + h * 68 + c0T);
                    float4 g4b = *reinterpret_cast<const float4*>(sG1 + jT * 136 + h * 68 + c0T + 4);
                    float4 q4a = *reinterpret_cast<const float4*>(sQa + n0q + c0T);
                    float4 q4b = *reinterpret_cast<const float4*>(sQa + n0q + c0T + 4);
                    const float4* kap = reinterpret_cast<const float4*>(g_ka + (size_t)(jbase + jT) * 256 + n0q + c0T);
                    float4 k4a = __ldg(kap), k4b = __ldg(kap + 1);
                    float v[8];
                    v[0] = fmaxf(g4a.x + q4a.x - k4a.x, 0.f);
                    v[1] = fmaxf(g4a.y + q4a.y - k4a.y, 0.f);
                    v[2] = fmaxf(g4a.z + q4a.z - k4a.z, 0.f);
                    v[3] = fmaxf(g4a.w + q4a.w - k4a.w, 0.f);
                    v[4] = fmaxf(g4b.x + q4b.x - k4b.x, 0.f);
                    v[5] = fmaxf(g4b.y + q4b.y - k4b.y, 0.f);
                    v[6] = fmaxf(g4b.z + q4b.z - k4b.z, 0.f);
                    v[7] = fmaxf(g4b.w + q4b.w - k4b.w, 0.f);
                    uint32_t ph[4], pl[4];
                    #pragma unroll
                    for (int t = 0; t < 4; ++t) {
                        __nv_bfloat16 a, b, al, bl;
                        split2(v[t * 2], a, al); split2(v[t * 2 + 1], b, bl);
                        ph[t] = pack_bf2(a, b); pl[t] = pack_bf2(al, bl);
                    }
                    *reinterpret_cast<uint4*>(sHidh + jT * 72 + c0T) = make_uint4(ph[0], ph[1], ph[2], ph[3]);
                    *reinterpret_cast<uint4*>(sHidl + jT * 72 + c0T) = make_uint4(pl[0], pl[1], pl[2], pl[3]);
                }
                __syncthreads();

                // GEMM2 strip s: sim += Hid @ W2T; warp = (g2m, g2n, g2k), no duplication
                #pragma unroll
                for (int kf = 0; kf < 2; ++kf) {
                    const int kloc = g2k * 32 + kf * 16;
                    wmma::load_matrix_sync(Ah0, sHidh + (g2m * 32) * 72 + kloc, 72);
                    wmma::load_matrix_sync(Ah1, sHidh + (g2m * 32 + 16) * 72 + kloc, 72);
                    wmma::load_matrix_sync(Al0, sHidl + (g2m * 32) * 72 + kloc, 72);
                    wmma::load_matrix_sync(Al1, sHidl + (g2m * 32 + 16) * 72 + kloc, 72);
                    wmma::load_matrix_sync(Cbh, sW2hi + (g2n * 16) * 264 + n0q + kloc, 264);
                    wmma::load_matrix_sync(Cbl, sW2lo + (g2n * 16) * 264 + n0q + kloc, 264);
                    MMA3(sim0, Ah0, Al0, Cbh, Cbl);
                    MMA3(sim1, Ah1, Al1, Cbh, Cbl);
                }
                __syncthreads();   // Hid reusable
            }
        }

        // ---- rpe = H @ pW2 on ALL 16 warps (16x16 tiles); Hid dead -> direct overlay store ----
        {
            wmma::fragment<wmma::accumulator, 16, 16, 16, float> racc;
            wmma::fill_fragment(racc, 0.f);
            #pragma unroll
            for (int k = 0; k < 4; ++k) {
                wmma::load_matrix_sync(Ah0, sHhi + rr * 72 + k * 16, 72);
                wmma::load_matrix_sync(Al0, sHlo + rr * 72 + k * 16, 72);
                wmma::load_matrix_sync(Bh, sWphi + k * 16 * 72 + rc, 72);
                wmma::load_matrix_sync(Bl, sWplo + k * 16 * 72 + rc, 72);
                wmma::mma_sync(racc, Ah0, Bh, racc);
                wmma::mma_sync(racc, Al0, Bh, racc);
                wmma::mma_sync(racc, Ah0, Bl, racc);
            }
            wmma::store_matrix_sync(sRpe + rr * 68 + rc, racc, 68, wmma::mem_row_major);
        }

        // ---- sim partial stores: k-half g2k -> G1 half (stride 136) ----
        wmma::store_matrix_sync(sG1 + (g2m * 32) * 136 + g2k * 68 + g2n * 16, sim0, 136, wmma::mem_row_major);
        wmma::store_matrix_sync(sG1 + (g2m * 32 + 16) * 136 + g2k * 68 + g2n * 16, sim1, 136, wmma::mem_row_major);
        __syncthreads();

        // ---- channel-wise online softmax over 64 j (8 j per thread) ----
        #pragma unroll
        for (int jj = 0; jj < 8; ++jj) {
            int j = jg * 8 + jj;
            float s  = sG1[j * 136 + d_e] + sG1[j * 136 + 68 + d_e];
            float vv = __ldg(g_vp + (size_t)(jbase + j) * 64 + d_e) + sRpe[j * 68 + d_e];
            float mn = fmaxf(m_run, s);
            float cs = __expf(m_run - mn);
            float pe = __expf(s - mn);
            l_run   = fmaf(l_run, cs, pe);
            num_run = fmaf(num_run, cs, pe * vv);
            m_run   = mn;
        }
    }

    // ---- final cross-group merge (8 groups; reuse G1) ----
    __syncthreads();
    float* sRed = sG1;
    sRed[jg * 64 + d_e]        = m_run;
    sRed[512 + jg * 64 + d_e]  = l_run;
    sRed[1024 + jg * 64 + d_e] = num_run;
    __syncthreads();
    if (tid < 64) {
        float M = -CUDART_INF_F;
        #pragma unroll
        for (int s2 = 0; s2 < 8; ++s2) M = fmaxf(M, sRed[s2 * 64 + tid]);
        float L = 0.f, NU = 0.f;
        #pragma unroll
        for (int s2 = 0; s2 < 8; ++s2) {
            float e = __expf(sRed[s2 * 64 + tid] - M);
            L  = fmaf(sRed[512 + s2 * 64 + tid], e, L);
            NU = fmaf(sRed[1024 + s2 * 64 + tid], e, NU);
        }
        out[i * 64 + tid] = NU / L;
    }
}

// ---------------- launch ----------------
extern "C" void kernel_launch(void* const* d_in, const int* in_sizes, int n_in,
                              void* d_out, int out_size) {
    const float* x   = (const float*)d_in[0];
    const float* pos = (const float*)d_in[1];
    const float* Wq  = (const float*)d_in[2];
    const float* Wk  = (const float*)d_in[3];
    const float* Wv  = (const float*)d_in[4];
    const float* pW1 = (const float*)d_in[5];
    const float* pb1 = (const float*)d_in[6];
    const float* pW2 = (const float*)d_in[7];
    const float* pb2 = (const float*)d_in[8];
    const float* aW1 = (const float*)d_in[9];
    const float* ab1 = (const float*)d_in[10];
    const float* aW2 = (const float*)d_in[11];
    // d_in[12] = ab2: constant over j per channel -> cancels in softmax (exact), unused.
    float* out = (float*)d_out;

    cudaFuncSetAttribute(pt_main, cudaFuncAttributeMaxDynamicSharedMemorySize, SMEM_BYTES);

    prep_pw2a<<<64, 256>>>(pW2, aW1);
    prep_qkv<<<NPTS, 256>>>(x, Wq, Wk, Wv, aW1, ab1, pb2);
    prep_wsplit<<<64, 256>>>(pW2, aW2);
    pt_main<<<NPTS, 512, SMEM_BYTES>>>(pos, pW1, pb1, out);
}